// round 12
// baseline (speedup 1.0000x reference)
#include <cuda_runtime.h>
#include <cuda_bf16.h>
#include <mma.h>
#include <math.h>
#include <stdint.h>

using namespace nvcuda;
typedef unsigned long long ull;

#define N_NODE   50000
#define N_EDGE   500000
#define N_QUERY  64
#define IN_DIM   128
#define OUT_DIM  128
#define ATTN_DIM 64
#define N_RELTOT 401
#define N_TAU    731
#define REC      192        // 64 attn cols + 128 projected-message cols
#define NROWPAD  50048      // 391 * 128

// ---- scratch (device globals) ----
__device__ float g_node[NROWPAD * REC];          // [hidden@Ws | hidden@Wh]
__device__ float g_rel [N_RELTOT * REC];         // [rela@Wr   | rela@Wh]
__device__ float g_tau [N_TAU    * REC];         // [h_tau@Wtau| h_tau@Wh]
__device__ float g_qpre[N_QUERY  * ATTN_DIM];
__device__ __nv_bfloat16 gAh[NROWPAD * IN_DIM];  // hidden hi
__device__ __nv_bfloat16 gAl[NROWPAD * IN_DIM];  // hidden lo
__device__ __nv_bfloat16 gBh[IN_DIM * REC];      // [Ws|Wh] hi, row-major [k][n]
__device__ __nv_bfloat16 gBl[IN_DIM * REC];      // [Ws|Wh] lo
// CSR machinery
__device__ int  g_cnt [N_NODE];
__device__ int  g_cnt2[N_NODE];
__device__ int  g_off [N_NODE + 1];
__device__ int4 g_emeta [N_EDGE];    // {r_idx | t<<16, rel, sub, obj}
__device__ int4 g_sorted[N_EDGE];

__device__ __forceinline__ void cvt_hilo(float v, unsigned short& h, unsigned short& l) {
    __nv_bfloat16 hb = __float2bfloat16_rn(v);
    __nv_bfloat16 lb = __float2bfloat16_rn(v - __bfloat162float(hb));
    h = __bfloat16_as_ushort(hb);
    l = __bfloat16_as_ushort(lb);
}

// ================= kernel Z: zero counters =================
__global__ void zero_cnt_kernel() {
    int i = blockIdx.x * blockDim.x + threadIdx.x;
    if (i < N_NODE) { g_cnt[i] = 0; g_cnt2[i] = 0; }
}

// ================= kernel 0: convert + meta/hist + small tables =================
// [0,320): convert hidden; [320,480): edge meta pack + histogram;
// 480: B convert; [481,582): rel 4/blk; [582,586): qpre; [586,1317): tau 1/blk
#define K_CV    320
#define K_META  (K_CV)             // 320
#define K_B     (K_META + 160)     // 480
#define K_REL   (K_B + 1)          // 481
#define K_QP    (K_REL + 101)      // 582
#define K_TAU   (K_QP + 4)         // 586
#define K_END   (K_TAU + 731)      // 1317

__global__ void __launch_bounds__(256)
prep_aux_kernel(const float* __restrict__ hidden,
                const float* __restrict__ rela,
                const int*   __restrict__ q_rel,
                const int*   __restrict__ q_tau,
                const int*   __restrict__ edges,
                const float* __restrict__ Ws,
                const float* __restrict__ Wr,
                const float* __restrict__ WqrW,
                const float* __restrict__ Wqrb,
                const float* __restrict__ Wtau,
                const float* __restrict__ Wh,
                const float* __restrict__ wt1,
                const float* __restrict__ bt1,
                const float* __restrict__ wt2,
                const float* __restrict__ bt2) {
    __shared__ float sh[16 * IN_DIM];
    const int tid = threadIdx.x;
    const int blk = blockIdx.x;

    if (blk < K_CV) {
        // ---- convert hidden (pad rows -> 0) ----
        const int total = NROWPAD * (IN_DIM / 4);
        const int stride = K_CV * 256;
        const float4* src = reinterpret_cast<const float4*>(hidden);
        ull* dh = reinterpret_cast<ull*>(gAh);
        ull* dl = reinterpret_cast<ull*>(gAl);
        const int limit = N_NODE * (IN_DIM / 4);
        for (int i = blk * 256 + tid; i < total; i += stride) {
            float4 v = (i < limit) ? src[i] : make_float4(0.f, 0.f, 0.f, 0.f);
            unsigned short h0, l0, h1, l1, h2, l2, h3, l3;
            cvt_hilo(v.x, h0, l0); cvt_hilo(v.y, h1, l1);
            cvt_hilo(v.z, h2, l2); cvt_hilo(v.w, h3, l3);
            dh[i] = (ull)h0 | ((ull)h1 << 16) | ((ull)h2 << 32) | ((ull)h3 << 48);
            dl[i] = (ull)l0 | ((ull)l1 << 16) | ((ull)l2 << 32) | ((ull)l3 << 48);
        }
    } else if (blk < K_B) {
        // ---- meta pack + histogram ----
        const int stride = 160 * 256;
        for (int e = (blk - K_META) * 256 + tid; e < N_EDGE; e += stride) {
            const int* er = edges + (size_t)e * 7;
            int r_idx = __ldg(er + 0);
            int rel   = __ldg(er + 2);
            int tauv  = __ldg(er + 4);
            int sub   = __ldg(er + 5);
            int obj   = __ldg(er + 6);
            int tq = __ldg(q_tau + r_idx);
            int t = (tauv >= 0 ? tauv - tq : 0) + 365;    // 0..730
            int4 m;
            m.x = r_idx | (t << 16);
            m.y = rel; m.z = sub; m.w = obj;
            g_emeta[e] = m;
            atomicAdd(&g_cnt[obj], 1);
        }
    } else if (blk == K_B) {
        // ---- convert B = [Ws|Wh] ----
        for (int i = tid; i < IN_DIM * REC; i += 256) {
            int k = i / REC, n = i - k * REC;
            float v = (n < 64) ? Ws[k * ATTN_DIM + n] : Wh[k * OUT_DIM + (n - 64)];
            unsigned short h, l;
            cvt_hilo(v, h, l);
            gBh[i] = __ushort_as_bfloat16(h);
            gBl[i] = __ushort_as_bfloat16(l);
        }
    } else if (blk < K_QP) {
        // ---- rel table: 4 rels per block ----
        const int rb = (blk - K_REL) * 4;
        for (int i = tid; i < 4 * IN_DIM; i += 256) {
            int rr = i >> 7, k = i & 127;
            int r = rb + rr;
            sh[rr * IN_DIM + k] = (r < N_RELTOT) ? rela[(size_t)r * IN_DIM + k] : 0.f;
        }
        __syncthreads();
        for (int o = tid; o < 4 * REC; o += 256) {
            int rr = o / REC, c = o - rr * REC;
            int r = rb + rr;
            if (r >= N_RELTOT) continue;
            const float* hrow = sh + rr * IN_DIM;
            float acc = 0.f;
            if (c < 64) {
#pragma unroll 8
                for (int k = 0; k < IN_DIM; k++)
                    acc = fmaf(hrow[k], __ldg(Wr + k * ATTN_DIM + c), acc);
            } else {
                const int cc = c - 64;
#pragma unroll 8
                for (int k = 0; k < IN_DIM; k++)
                    acc = fmaf(hrow[k], __ldg(Wh + k * OUT_DIM + cc), acc);
            }
            g_rel[r * REC + c] = acc;
        }
    } else if (blk < K_TAU) {
        // ---- qpre: 16 queries per block ----
        const int qb = (blk - K_QP) * 16;
        for (int i = tid; i < 16 * IN_DIM; i += 256) {
            int qq = i >> 7, k = i & 127;
            int q = qb + qq;
            int rl = (q < N_QUERY) ? __ldg(q_rel + q) : 0;
            sh[qq * IN_DIM + k] = rela[(size_t)rl * IN_DIM + k];
        }
        __syncthreads();
        for (int o = tid; o < 16 * ATTN_DIM; o += 256) {
            int qq = o >> 6, c = o & 63;
            int q = qb + qq;
            if (q >= N_QUERY) continue;
            const float* hrow = sh + qq * IN_DIM;
            float acc = __ldg(Wqrb + c);
#pragma unroll 8
            for (int k = 0; k < IN_DIM; k++)
                acc = fmaf(hrow[k], __ldg(WqrW + k * ATTN_DIM + c), acc);
            g_qpre[q * ATTN_DIM + c] = acc;
        }
    } else {
        // ---- tau table: one t per block ----
        const int t = blk - K_TAU;
        const float dt = (float)(t - 365);
        if (tid < IN_DIM)
            sh[tid] = wt1[tid] * dt + bt1[tid] + sinf(fmaf(wt2[tid], dt, bt2[tid]));
        __syncthreads();
        if (tid < REC) {
            const int c = tid;
            float acc = 0.f;
            if (c < 64) {
#pragma unroll 8
                for (int k = 0; k < IN_DIM; k++)
                    acc = fmaf(sh[k], __ldg(Wtau + k * ATTN_DIM + c), acc);
            } else {
                const int cc = c - 64;
#pragma unroll 8
                for (int k = 0; k < IN_DIM; k++)
                    acc = fmaf(sh[k], __ldg(Wh + k * OUT_DIM + cc), acc);
            }
            g_tau[t * REC + c] = acc;
        }
    }
}

// ================= kernel: exclusive scan of g_cnt -> g_off =================
__global__ void __launch_bounds__(1024)
scan_kernel() {
    __shared__ int ssum[1024];
    __shared__ int s_carry;
    const int tid = threadIdx.x;
    if (tid == 0) s_carry = 0;
    __syncthreads();
    const int nchunk = (N_NODE + 1023) / 1024;
    for (int c = 0; c < nchunk; c++) {
        int idx = c * 1024 + tid;
        int v = (idx < N_NODE) ? g_cnt[idx] : 0;
        ssum[tid] = v;
        __syncthreads();
#pragma unroll
        for (int d = 1; d < 1024; d <<= 1) {
            int t = (tid >= d) ? ssum[tid - d] : 0;
            __syncthreads();
            ssum[tid] += t;
            __syncthreads();
        }
        if (idx < N_NODE) g_off[idx] = s_carry + ssum[tid] - v;
        __syncthreads();
        if (tid == 0) s_carry += ssum[1023];
        __syncthreads();
    }
    if (tid == 0) g_off[N_NODE] = s_carry;    // == N_EDGE
}

// ================= kernel: scatter edges into CSR order =================
__global__ void __launch_bounds__(256)
scatter_kernel() {
    const int stride = gridDim.x * blockDim.x;
    for (int e = blockIdx.x * blockDim.x + threadIdx.x; e < N_EDGE; e += stride) {
        int4 m = g_emeta[e];
        int obj = m.w;
        int pos = g_off[obj] + atomicAdd(&g_cnt2[obj], 1);
        g_sorted[pos] = m;
    }
}

// ================= kernel 1: persistent node GEMM (unchanged) =================
#define N_TILE   391
#define GB       131
#define TPB      3
#define LDA 136
#define LDB 200
#define SA_H 0
#define SA_L (SA_H + 128 * LDA * 2)
#define SB_H (SA_L + 128 * LDA * 2)
#define SB_L (SB_H + 128 * LDB * 2)
#define SM1_TOT (SB_L + 128 * LDB * 2)     // 172032

__global__ void __launch_bounds__(256)
node_gemm_kernel() {
    extern __shared__ char smem[];
    __nv_bfloat16* Ah = reinterpret_cast<__nv_bfloat16*>(smem + SA_H);
    __nv_bfloat16* Al = reinterpret_cast<__nv_bfloat16*>(smem + SA_L);
    __nv_bfloat16* Bh = reinterpret_cast<__nv_bfloat16*>(smem + SB_H);
    __nv_bfloat16* Bl = reinterpret_cast<__nv_bfloat16*>(smem + SB_L);
    const int tid = threadIdx.x;
    const int wid = tid >> 5;

    {
        const float4* sh4 = reinterpret_cast<const float4*>(gBh);
        const float4* sl4 = reinterpret_cast<const float4*>(gBl);
        for (int i = tid; i < 128 * 24; i += 256) {
            int k = i / 24, c = i - k * 24;
            *reinterpret_cast<float4*>(Bh + k * LDB + c * 8) = sh4[k * 24 + c];
            *reinterpret_cast<float4*>(Bl + k * LDB + c * 8) = sl4[k * 24 + c];
        }
    }

    wmma::fragment<wmma::matrix_a, 16, 16, 16, __nv_bfloat16, wmma::row_major> fah, fal;
    wmma::fragment<wmma::matrix_b, 16, 16, 16, __nv_bfloat16, wmma::row_major> fbh, fbl;

    for (int s = 0; s < TPB; s++) {
        const int tile = blockIdx.x * TPB + s;
        if (tile >= N_TILE) break;
        const int r0 = tile * 128;

        __syncthreads();
        {
            const float4* ah4 = reinterpret_cast<const float4*>(gAh);
            const float4* al4 = reinterpret_cast<const float4*>(gAl);
            for (int i = tid; i < 128 * 16; i += 256) {
                int row = i >> 4, c = i & 15;
                *reinterpret_cast<float4*>(Ah + row * LDA + c * 8) = ah4[(size_t)(r0 + row) * 16 + c];
                *reinterpret_cast<float4*>(Al + row * LDA + c * 8) = al4[(size_t)(r0 + row) * 16 + c];
            }
        }
        __syncthreads();

        wmma::fragment<wmma::accumulator, 16, 16, 16, float> acc[12];
#pragma unroll
        for (int ct = 0; ct < 12; ct++) wmma::fill_fragment(acc[ct], 0.f);

#pragma unroll
        for (int ks = 0; ks < 8; ks++) {
            wmma::load_matrix_sync(fah, Ah + wid * 16 * LDA + ks * 16, LDA);
            wmma::load_matrix_sync(fal, Al + wid * 16 * LDA + ks * 16, LDA);
#pragma unroll
            for (int ct = 0; ct < 12; ct++) {
                wmma::load_matrix_sync(fbh, Bh + ks * 16 * LDB + ct * 16, LDB);
                wmma::load_matrix_sync(fbl, Bl + ks * 16 * LDB + ct * 16, LDB);
                wmma::mma_sync(acc[ct], fah, fbh, acc[ct]);
                wmma::mma_sync(acc[ct], fah, fbl, acc[ct]);
                wmma::mma_sync(acc[ct], fal, fbh, acc[ct]);
            }
        }
        float* dst = g_node + (size_t)(r0 + wid * 16) * REC;
#pragma unroll
        for (int ct = 0; ct < 12; ct++)
            wmma::store_matrix_sync(dst + ct * 16, acc[ct], REC, wmma::mem_row_major);
    }
}

// ================= accumulate kernel: one 16-lane group per node =================
__global__ void __launch_bounds__(256)
accum_kernel(const float* __restrict__ waW,
             const float* __restrict__ wab,
             float* __restrict__ out) {
    const int tid = threadIdx.x;
    const int g   = tid >> 4;            // group 0..15 within block
    const int sl  = tid & 15;
    const int n   = blockIdx.x * 16 + g; // node (grid = 3125 -> covers 50000 exactly)
    const unsigned mask = 0xFFFFu << (((tid >> 4) & 1) * 16);

    const int beg = g_off[n];
    const int end = g_off[n + 1];

    const float4 w  = reinterpret_cast<const float4*>(waW)[sl];
    const float  wb = __ldg(wab);

    float4 acc0 = make_float4(0.f, 0.f, 0.f, 0.f);
    float4 acc1 = make_float4(0.f, 0.f, 0.f, 0.f);

    for (int i = beg; i < end; i++) {
        const int4 m = g_sorted[i];                // broadcast across group
        const int r_idx = m.x & 0xFFFF;
        const int t     = m.x >> 16;
        const int rel   = m.y;
        const int sub   = m.z;

        const float4* np = reinterpret_cast<const float4*>(g_node + (size_t)sub * REC);
        const float4* rp = reinterpret_cast<const float4*>(g_rel  + rel   * REC);
        const float4* tp = reinterpret_cast<const float4*>(g_tau  + t     * REC);
        const float4* qp = reinterpret_cast<const float4*>(g_qpre + r_idx * ATTN_DIM);

        // attention: 64-wide, 4 per lane
        float4 a = np[sl], b = rp[sl], cq = qp[sl], d = tp[sl];
        float p0 = fmaxf(a.x + b.x + cq.x + d.x, 0.f);
        float p1 = fmaxf(a.y + b.y + cq.y + d.y, 0.f);
        float p2 = fmaxf(a.z + b.z + cq.z + d.z, 0.f);
        float p3 = fmaxf(a.w + b.w + cq.w + d.w, 0.f);
        float s = fmaf(p0, w.x, fmaf(p1, w.y, fmaf(p2, w.z, p3 * w.w)));
#pragma unroll
        for (int off = 8; off > 0; off >>= 1)
            s += __shfl_xor_sync(mask, s, off);
        const float alpha = 1.f / (1.f + __expf(-(s + wb)));

        // projected message: 128-wide, 8 per lane
        const int mo = 16 + sl * 2;
        float4 n0 = np[mo], n1 = np[mo + 1];
        float4 r0 = rp[mo], r1 = rp[mo + 1];
        float4 t0 = tp[mo], t1 = tp[mo + 1];

        acc0.x = fmaf(alpha, n0.x + r0.x + t0.x, acc0.x);
        acc0.y = fmaf(alpha, n0.y + r0.y + t0.y, acc0.y);
        acc0.z = fmaf(alpha, n0.z + r0.z + t0.z, acc0.z);
        acc0.w = fmaf(alpha, n0.w + r0.w + t0.w, acc0.w);
        acc1.x = fmaf(alpha, n1.x + r1.x + t1.x, acc1.x);
        acc1.y = fmaf(alpha, n1.y + r1.y + t1.y, acc1.y);
        acc1.z = fmaf(alpha, n1.z + r1.z + t1.z, acc1.z);
        acc1.w = fmaf(alpha, n1.w + r1.w + t1.w, acc1.w);
    }

    float4* dst = reinterpret_cast<float4*>(out + (size_t)n * OUT_DIM + sl * 8);
    dst[0] = acc0;
    dst[1] = acc1;
}

// ================= launcher =================
extern "C" void kernel_launch(void* const* d_in, const int* in_sizes, int n_in,
                              void* d_out, int out_size) {
    int base = 5;
    if (n_in > 5 && in_sizes[5] == 1) base = 6;

    const int*   q_rel  = (const int*)  d_in[1];
    const int*   q_tau  = (const int*)  d_in[2];
    const float* hidden = (const float*)d_in[3];
    const int*   edges  = (const int*)  d_in[4];
    const float* rela   = (const float*)d_in[base + 1];
    const float* Ws     = (const float*)d_in[base + 2];
    const float* Wr     = (const float*)d_in[base + 3];
    const float* WqrW   = (const float*)d_in[base + 4];
    const float* Wqrb   = (const float*)d_in[base + 5];
    const float* Wtau   = (const float*)d_in[base + 6];
    const float* waW    = (const float*)d_in[base + 7];
    const float* wab    = (const float*)d_in[base + 8];
    const float* Wh     = (const float*)d_in[base + 9];
    const float* wt1    = (const float*)d_in[base + 10];
    const float* bt1    = (const float*)d_in[base + 11];
    const float* wt2    = (const float*)d_in[base + 12];
    const float* bt2    = (const float*)d_in[base + 13];
    float* out = (float*)d_out;

    cudaFuncSetAttribute(node_gemm_kernel,
                         cudaFuncAttributeMaxDynamicSharedMemorySize, SM1_TOT);

    zero_cnt_kernel<<<(N_NODE + 255) / 256, 256>>>();

    prep_aux_kernel<<<K_END, 256>>>(
        hidden, rela, q_rel, q_tau, edges, Ws, Wr, WqrW, Wqrb, Wtau, Wh,
        wt1, bt1, wt2, bt2);

    scan_kernel<<<1, 1024>>>();
    scatter_kernel<<<489, 256>>>();

    node_gemm_kernel<<<GB, 256, SM1_TOT>>>();

    accum_kernel<<<N_NODE / 16, 256>>>(waW, wab, out);
}

// round 13
// speedup vs baseline: 1.3460x; 1.3460x over previous
#include <cuda_runtime.h>
#include <cuda_bf16.h>
#include <mma.h>
#include <math.h>
#include <stdint.h>

using namespace nvcuda;
typedef unsigned long long ull;

#define N_NODE   50000
#define N_EDGE   500000
#define N_QUERY  64
#define IN_DIM   128
#define OUT_DIM  128
#define ATTN_DIM 64
#define N_RELTOT 401
#define N_TAU    731
#define REC      192
#define NROWPAD  50048      // 391 * 128
#define NSCB     49         // scan blocks of 1024 covering 50000

// ---- scratch (device globals) ----
__device__ float g_node[NROWPAD * REC];
__device__ float g_rel [N_RELTOT * REC];
__device__ float g_tau [N_TAU    * REC];
__device__ float g_qpre[N_QUERY  * ATTN_DIM];
__device__ __nv_bfloat16 gAh[NROWPAD * IN_DIM];
__device__ __nv_bfloat16 gAl[NROWPAD * IN_DIM];
__device__ __nv_bfloat16 gBh[IN_DIM * REC];
__device__ __nv_bfloat16 gBl[IN_DIM * REC];
// CSR machinery
__device__ int  g_cnt [N_NODE];
__device__ int  g_cnt2[N_NODE];
__device__ int  g_off [N_NODE + 1];
__device__ int  g_bsum [NSCB];
__device__ int  g_bscan[NSCB];
__device__ int4 g_emeta [N_EDGE];    // {r_idx | t<<16, rel, sub, obj}
__device__ int4 g_sorted[N_EDGE];

__device__ __forceinline__ void cvt_hilo(float v, unsigned short& h, unsigned short& l) {
    __nv_bfloat16 hb = __float2bfloat16_rn(v);
    __nv_bfloat16 lb = __float2bfloat16_rn(v - __bfloat162float(hb));
    h = __bfloat16_as_ushort(hb);
    l = __bfloat16_as_ushort(lb);
}

// ================= CSR chain (stream s1) =================
__global__ void zero_cnt_kernel() {
    int i = blockIdx.x * blockDim.x + threadIdx.x;
    if (i < N_NODE) { g_cnt[i] = 0; g_cnt2[i] = 0; }
}

__global__ void __launch_bounds__(256)
meta_hist_kernel(const int* __restrict__ edges, const int* __restrict__ q_tau) {
    const int stride = gridDim.x * blockDim.x;
    for (int e = blockIdx.x * blockDim.x + threadIdx.x; e < N_EDGE; e += stride) {
        const int* er = edges + (size_t)e * 7;
        int r_idx = __ldg(er + 0);
        int rel   = __ldg(er + 2);
        int tauv  = __ldg(er + 4);
        int sub   = __ldg(er + 5);
        int obj   = __ldg(er + 6);
        int tq = __ldg(q_tau + r_idx);
        int t = (tauv >= 0 ? tauv - tq : 0) + 365;    // 0..730
        int4 m;
        m.x = r_idx | (t << 16);
        m.y = rel; m.z = sub; m.w = obj;
        g_emeta[e] = m;
        atomicAdd(&g_cnt[obj], 1);
    }
}

__global__ void __launch_bounds__(1024)
scan_local_kernel() {
    __shared__ int ss[1024];
    const int tid = threadIdx.x;
    const int idx = blockIdx.x * 1024 + tid;
    int v = (idx < N_NODE) ? g_cnt[idx] : 0;
    ss[tid] = v;
    __syncthreads();
#pragma unroll
    for (int d = 1; d < 1024; d <<= 1) {
        int t = (tid >= d) ? ss[tid - d] : 0;
        __syncthreads();
        ss[tid] += t;
        __syncthreads();
    }
    if (idx < N_NODE) g_off[idx] = ss[tid] - v;     // exclusive within block
    if (tid == 1023) g_bsum[blockIdx.x] = ss[1023];
}

__global__ void __launch_bounds__(64)
scan_tot_kernel() {
    __shared__ int ss[64];
    const int tid = threadIdx.x;
    int v = (tid < NSCB) ? g_bsum[tid] : 0;
    ss[tid] = v;
    __syncthreads();
#pragma unroll
    for (int d = 1; d < 64; d <<= 1) {
        int t = (tid >= d) ? ss[tid - d] : 0;
        __syncthreads();
        ss[tid] += t;
        __syncthreads();
    }
    if (tid < NSCB) g_bscan[tid] = ss[tid] - v;
    if (tid == 63) g_off[N_NODE] = ss[63];          // == N_EDGE
}

__global__ void __launch_bounds__(1024)
scan_add_kernel() {
    const int idx = blockIdx.x * 1024 + threadIdx.x;
    if (idx < N_NODE) g_off[idx] += g_bscan[blockIdx.x];
}

__global__ void __launch_bounds__(256)
scatter_kernel() {
    const int stride = gridDim.x * blockDim.x;
    for (int e = blockIdx.x * blockDim.x + threadIdx.x; e < N_EDGE; e += stride) {
        int4 m = g_emeta[e];
        int pos = g_off[m.w] + atomicAdd(&g_cnt2[m.w], 1);
        g_sorted[pos] = m;
    }
}

// ================= prep_main (stream 0): convert + tables =================
// [0,320): convert hidden; 320: B convert; [321,422): rel 4/blk;
// [422,426): qpre; [426,1157): tau 1/blk
#define K_CV   320
#define K_B    (K_CV)             // 320
#define K_REL  (K_B + 1)          // 321
#define K_QP   (K_REL + 101)      // 422
#define K_TAU  (K_QP + 4)         // 426
#define K_END  (K_TAU + 731)      // 1157

__global__ void __launch_bounds__(256)
prep_main_kernel(const float* __restrict__ hidden,
                 const float* __restrict__ rela,
                 const int*   __restrict__ q_rel,
                 const float* __restrict__ Ws,
                 const float* __restrict__ Wr,
                 const float* __restrict__ WqrW,
                 const float* __restrict__ Wqrb,
                 const float* __restrict__ Wtau,
                 const float* __restrict__ Wh,
                 const float* __restrict__ wt1,
                 const float* __restrict__ bt1,
                 const float* __restrict__ wt2,
                 const float* __restrict__ bt2) {
    __shared__ float sh[16 * IN_DIM];
    const int tid = threadIdx.x;
    const int blk = blockIdx.x;

    if (blk < K_CV) {
        const int total = NROWPAD * (IN_DIM / 4);
        const int stride = K_CV * 256;
        const float4* src = reinterpret_cast<const float4*>(hidden);
        ull* dh = reinterpret_cast<ull*>(gAh);
        ull* dl = reinterpret_cast<ull*>(gAl);
        const int limit = N_NODE * (IN_DIM / 4);
        for (int i = blk * 256 + tid; i < total; i += stride) {
            float4 v = (i < limit) ? src[i] : make_float4(0.f, 0.f, 0.f, 0.f);
            unsigned short h0, l0, h1, l1, h2, l2, h3, l3;
            cvt_hilo(v.x, h0, l0); cvt_hilo(v.y, h1, l1);
            cvt_hilo(v.z, h2, l2); cvt_hilo(v.w, h3, l3);
            dh[i] = (ull)h0 | ((ull)h1 << 16) | ((ull)h2 << 32) | ((ull)h3 << 48);
            dl[i] = (ull)l0 | ((ull)l1 << 16) | ((ull)l2 << 32) | ((ull)l3 << 48);
        }
    } else if (blk == K_B) {
        for (int i = tid; i < IN_DIM * REC; i += 256) {
            int k = i / REC, n = i - k * REC;
            float v = (n < 64) ? Ws[k * ATTN_DIM + n] : Wh[k * OUT_DIM + (n - 64)];
            unsigned short h, l;
            cvt_hilo(v, h, l);
            gBh[i] = __ushort_as_bfloat16(h);
            gBl[i] = __ushort_as_bfloat16(l);
        }
    } else if (blk < K_QP) {
        const int rb = (blk - K_REL) * 4;
        for (int i = tid; i < 4 * IN_DIM; i += 256) {
            int rr = i >> 7, k = i & 127;
            int r = rb + rr;
            sh[rr * IN_DIM + k] = (r < N_RELTOT) ? rela[(size_t)r * IN_DIM + k] : 0.f;
        }
        __syncthreads();
        for (int o = tid; o < 4 * REC; o += 256) {
            int rr = o / REC, c = o - rr * REC;
            int r = rb + rr;
            if (r >= N_RELTOT) continue;
            const float* hrow = sh + rr * IN_DIM;
            float acc = 0.f;
            if (c < 64) {
#pragma unroll 8
                for (int k = 0; k < IN_DIM; k++)
                    acc = fmaf(hrow[k], __ldg(Wr + k * ATTN_DIM + c), acc);
            } else {
                const int cc = c - 64;
#pragma unroll 8
                for (int k = 0; k < IN_DIM; k++)
                    acc = fmaf(hrow[k], __ldg(Wh + k * OUT_DIM + cc), acc);
            }
            g_rel[r * REC + c] = acc;
        }
    } else if (blk < K_TAU) {
        const int qb = (blk - K_QP) * 16;
        for (int i = tid; i < 16 * IN_DIM; i += 256) {
            int qq = i >> 7, k = i & 127;
            int q = qb + qq;
            int rl = (q < N_QUERY) ? __ldg(q_rel + q) : 0;
            sh[qq * IN_DIM + k] = rela[(size_t)rl * IN_DIM + k];
        }
        __syncthreads();
        for (int o = tid; o < 16 * ATTN_DIM; o += 256) {
            int qq = o >> 6, c = o & 63;
            int q = qb + qq;
            if (q >= N_QUERY) continue;
            const float* hrow = sh + qq * IN_DIM;
            float acc = __ldg(Wqrb + c);
#pragma unroll 8
            for (int k = 0; k < IN_DIM; k++)
                acc = fmaf(hrow[k], __ldg(WqrW + k * ATTN_DIM + c), acc);
            g_qpre[q * ATTN_DIM + c] = acc;
        }
    } else {
        const int t = blk - K_TAU;
        const float dt = (float)(t - 365);
        if (tid < IN_DIM)
            sh[tid] = wt1[tid] * dt + bt1[tid] + sinf(fmaf(wt2[tid], dt, bt2[tid]));
        __syncthreads();
        if (tid < REC) {
            const int c = tid;
            float acc = 0.f;
            if (c < 64) {
#pragma unroll 8
                for (int k = 0; k < IN_DIM; k++)
                    acc = fmaf(sh[k], __ldg(Wtau + k * ATTN_DIM + c), acc);
            } else {
                const int cc = c - 64;
#pragma unroll 8
                for (int k = 0; k < IN_DIM; k++)
                    acc = fmaf(sh[k], __ldg(Wh + k * OUT_DIM + cc), acc);
            }
            g_tau[t * REC + c] = acc;
        }
    }
}

// ================= node GEMM (unchanged) =================
#define N_TILE   391
#define GB       131
#define TPB      3
#define LDA 136
#define LDB 200
#define SA_H 0
#define SA_L (SA_H + 128 * LDA * 2)
#define SB_H (SA_L + 128 * LDA * 2)
#define SB_L (SB_H + 128 * LDB * 2)
#define SM1_TOT (SB_L + 128 * LDB * 2)     // 172032

__global__ void __launch_bounds__(256)
node_gemm_kernel() {
    extern __shared__ char smem[];
    __nv_bfloat16* Ah = reinterpret_cast<__nv_bfloat16*>(smem + SA_H);
    __nv_bfloat16* Al = reinterpret_cast<__nv_bfloat16*>(smem + SA_L);
    __nv_bfloat16* Bh = reinterpret_cast<__nv_bfloat16*>(smem + SB_H);
    __nv_bfloat16* Bl = reinterpret_cast<__nv_bfloat16*>(smem + SB_L);
    const int tid = threadIdx.x;
    const int wid = tid >> 5;

    {
        const float4* sh4 = reinterpret_cast<const float4*>(gBh);
        const float4* sl4 = reinterpret_cast<const float4*>(gBl);
        for (int i = tid; i < 128 * 24; i += 256) {
            int k = i / 24, c = i - k * 24;
            *reinterpret_cast<float4*>(Bh + k * LDB + c * 8) = sh4[k * 24 + c];
            *reinterpret_cast<float4*>(Bl + k * LDB + c * 8) = sl4[k * 24 + c];
        }
    }

    wmma::fragment<wmma::matrix_a, 16, 16, 16, __nv_bfloat16, wmma::row_major> fah, fal;
    wmma::fragment<wmma::matrix_b, 16, 16, 16, __nv_bfloat16, wmma::row_major> fbh, fbl;

    for (int s = 0; s < TPB; s++) {
        const int tile = blockIdx.x * TPB + s;
        if (tile >= N_TILE) break;
        const int r0 = tile * 128;

        __syncthreads();
        {
            const float4* ah4 = reinterpret_cast<const float4*>(gAh);
            const float4* al4 = reinterpret_cast<const float4*>(gAl);
            for (int i = tid; i < 128 * 16; i += 256) {
                int row = i >> 4, c = i & 15;
                *reinterpret_cast<float4*>(Ah + row * LDA + c * 8) = ah4[(size_t)(r0 + row) * 16 + c];
                *reinterpret_cast<float4*>(Al + row * LDA + c * 8) = al4[(size_t)(r0 + row) * 16 + c];
            }
        }
        __syncthreads();

        wmma::fragment<wmma::accumulator, 16, 16, 16, float> acc[12];
#pragma unroll
        for (int ct = 0; ct < 12; ct++) wmma::fill_fragment(acc[ct], 0.f);

#pragma unroll
        for (int ks = 0; ks < 8; ks++) {
            wmma::load_matrix_sync(fah, Ah + wid * 16 * LDA + ks * 16, LDA);
            wmma::load_matrix_sync(fal, Al + wid * 16 * LDA + ks * 16, LDA);
#pragma unroll
            for (int ct = 0; ct < 12; ct++) {
                wmma::load_matrix_sync(fbh, Bh + ks * 16 * LDB + ct * 16, LDB);
                wmma::load_matrix_sync(fbl, Bl + ks * 16 * LDB + ct * 16, LDB);
                wmma::mma_sync(acc[ct], fah, fbh, acc[ct]);
                wmma::mma_sync(acc[ct], fah, fbl, acc[ct]);
                wmma::mma_sync(acc[ct], fal, fbh, acc[ct]);
            }
        }
        float* dst = g_node + (size_t)(r0 + wid * 16) * REC;
#pragma unroll
        for (int ct = 0; ct < 12; ct++)
            wmma::store_matrix_sync(dst + ct * 16, acc[ct], REC, wmma::mem_row_major);
    }
}

// ================= accum: one 16-lane group per node, no atomics =================
__global__ void __launch_bounds__(256)
accum_kernel(const float* __restrict__ waW,
             const float* __restrict__ wab,
             float* __restrict__ out) {
    const int tid = threadIdx.x;
    const int g   = tid >> 4;
    const int sl  = tid & 15;
    const int n   = blockIdx.x * 16 + g;          // grid 3125 covers 50000 exactly
    const unsigned mask = 0xFFFFu << (((tid >> 4) & 1) * 16);

    const int beg = g_off[n];
    const int end = g_off[n + 1];

    const float4 w  = reinterpret_cast<const float4*>(waW)[sl];
    const float  wb = __ldg(wab);

    float4 acc0 = make_float4(0.f, 0.f, 0.f, 0.f);
    float4 acc1 = make_float4(0.f, 0.f, 0.f, 0.f);

    for (int i = beg; i < end; i++) {
        const int4 m = g_sorted[i];
        const int r_idx = m.x & 0xFFFF;
        const int t     = m.x >> 16;
        const int rel   = m.y;
        const int sub   = m.z;

        const float4* np = reinterpret_cast<const float4*>(g_node + (size_t)sub * REC);
        const float4* rp = reinterpret_cast<const float4*>(g_rel  + rel   * REC);
        const float4* tp = reinterpret_cast<const float4*>(g_tau  + t     * REC);
        const float4* qp = reinterpret_cast<const float4*>(g_qpre + r_idx * ATTN_DIM);

        float4 a = np[sl], b = rp[sl], cq = qp[sl], d = tp[sl];
        float p0 = fmaxf(a.x + b.x + cq.x + d.x, 0.f);
        float p1 = fmaxf(a.y + b.y + cq.y + d.y, 0.f);
        float p2 = fmaxf(a.z + b.z + cq.z + d.z, 0.f);
        float p3 = fmaxf(a.w + b.w + cq.w + d.w, 0.f);
        float s = fmaf(p0, w.x, fmaf(p1, w.y, fmaf(p2, w.z, p3 * w.w)));
#pragma unroll
        for (int off = 8; off > 0; off >>= 1)
            s += __shfl_xor_sync(mask, s, off);
        const float alpha = 1.f / (1.f + __expf(-(s + wb)));

        const int mo = 16 + sl * 2;
        float4 n0 = np[mo], n1 = np[mo + 1];
        float4 r0 = rp[mo], r1 = rp[mo + 1];
        float4 t0 = tp[mo], t1 = tp[mo + 1];

        acc0.x = fmaf(alpha, n0.x + r0.x + t0.x, acc0.x);
        acc0.y = fmaf(alpha, n0.y + r0.y + t0.y, acc0.y);
        acc0.z = fmaf(alpha, n0.z + r0.z + t0.z, acc0.z);
        acc0.w = fmaf(alpha, n0.w + r0.w + t0.w, acc0.w);
        acc1.x = fmaf(alpha, n1.x + r1.x + t1.x, acc1.x);
        acc1.y = fmaf(alpha, n1.y + r1.y + t1.y, acc1.y);
        acc1.z = fmaf(alpha, n1.z + r1.z + t1.z, acc1.z);
        acc1.w = fmaf(alpha, n1.w + r1.w + t1.w, acc1.w);
    }

    float4* dst = reinterpret_cast<float4*>(out + (size_t)n * OUT_DIM + sl * 8);
    dst[0] = acc0;
    dst[1] = acc1;
}

// ================= launcher =================
extern "C" void kernel_launch(void* const* d_in, const int* in_sizes, int n_in,
                              void* d_out, int out_size) {
    int base = 5;
    if (n_in > 5 && in_sizes[5] == 1) base = 6;

    const int*   q_rel  = (const int*)  d_in[1];
    const int*   q_tau  = (const int*)  d_in[2];
    const float* hidden = (const float*)d_in[3];
    const int*   edges  = (const int*)  d_in[4];
    const float* rela   = (const float*)d_in[base + 1];
    const float* Ws     = (const float*)d_in[base + 2];
    const float* Wr     = (const float*)d_in[base + 3];
    const float* WqrW   = (const float*)d_in[base + 4];
    const float* Wqrb   = (const float*)d_in[base + 5];
    const float* Wtau   = (const float*)d_in[base + 6];
    const float* waW    = (const float*)d_in[base + 7];
    const float* wab    = (const float*)d_in[base + 8];
    const float* Wh     = (const float*)d_in[base + 9];
    const float* wt1    = (const float*)d_in[base + 10];
    const float* bt1    = (const float*)d_in[base + 11];
    const float* wt2    = (const float*)d_in[base + 12];
    const float* bt2    = (const float*)d_in[base + 13];
    float* out = (float*)d_out;

    cudaFuncSetAttribute(node_gemm_kernel,
                         cudaFuncAttributeMaxDynamicSharedMemorySize, SM1_TOT);

    // one-time resource init (host objects only; no device memory)
    static cudaStream_t s1 = nullptr;
    static cudaEvent_t evFork = nullptr, evJoin = nullptr;
    if (s1 == nullptr) {
        cudaStreamCreateWithFlags(&s1, cudaStreamNonBlocking);
        cudaEventCreateWithFlags(&evFork, cudaEventDisableTiming);
        cudaEventCreateWithFlags(&evJoin, cudaEventDisableTiming);
    }

    // fork s1 off the (captured) default stream
    cudaEventRecord(evFork, 0);
    cudaStreamWaitEvent(s1, evFork, 0);

    // ---- s1: CSR chain (no smem -> coexists with gemm) ----
    zero_cnt_kernel<<<(N_NODE + 255) / 256, 256, 0, s1>>>();
    meta_hist_kernel<<<160, 256, 0, s1>>>(edges, q_tau);
    scan_local_kernel<<<NSCB, 1024, 0, s1>>>();
    scan_tot_kernel<<<1, 64, 0, s1>>>();
    scan_add_kernel<<<NSCB, 1024, 0, s1>>>();
    scatter_kernel<<<977, 256, 0, s1>>>();
    cudaEventRecord(evJoin, s1);

    // ---- s0: main chain ----
    prep_main_kernel<<<K_END, 256>>>(
        hidden, rela, q_rel, Ws, Wr, WqrW, Wqrb, Wtau, Wh,
        wt1, bt1, wt2, bt2);
    node_gemm_kernel<<<GB, 256, SM1_TOT>>>();

    // join and accumulate
    cudaStreamWaitEvent(0, evJoin, 0);
    accum_kernel<<<N_NODE / 16, 256>>>(waW, wab, out);
}

// round 15
// speedup vs baseline: 1.4781x; 1.0982x over previous
#include <cuda_runtime.h>
#include <cuda_bf16.h>
#include <cuda_fp16.h>
#include <mma.h>
#include <math.h>
#include <stdint.h>

using namespace nvcuda;
typedef unsigned long long ull;

#define N_NODE   50000
#define N_EDGE   500000
#define N_QUERY  64
#define IN_DIM   128
#define OUT_DIM  128
#define ATTN_DIM 64
#define N_RELTOT 401
#define N_TAU    731
#define REC      192        // 64 attn cols + 128 projected-message cols
#define NROWPAD  50048      // 391 * 128

// ---- scratch (device globals) ----
__device__ float g_node[NROWPAD * REC];          // [hidden@Ws | hidden@Wh]
__device__ float g_rel [N_RELTOT * REC];
__device__ float g_tau [N_TAU    * REC];
__device__ float g_qpre[N_QUERY  * ATTN_DIM];
__device__ __nv_bfloat16 gAh[NROWPAD * IN_DIM];
__device__ __nv_bfloat16 gAl[NROWPAD * IN_DIM];
__device__ __nv_bfloat16 gBh[IN_DIM * REC];
__device__ __nv_bfloat16 gBl[IN_DIM * REC];
// fp16 attention side-tables (halved gather traffic in the edge kernel)
__device__ __align__(16) __half h_nA[NROWPAD  * ATTN_DIM];
__device__ __align__(16) __half h_rA[N_RELTOT * ATTN_DIM];
__device__ __align__(16) __half h_tA[N_TAU    * ATTN_DIM];
__device__ __align__(16) __half h_qA[N_QUERY  * ATTN_DIM];

__device__ __forceinline__ void cvt_hilo(float v, unsigned short& h, unsigned short& l) {
    __nv_bfloat16 hb = __float2bfloat16_rn(v);
    __nv_bfloat16 lb = __float2bfloat16_rn(v - __bfloat162float(hb));
    h = __bfloat16_as_ushort(hb);
    l = __bfloat16_as_ushort(lb);
}

// ================= kernel 0: convert + small tables =================
// [0,320): convert hidden; 320: B convert; [321,422): rel 4/blk;
// [422,426): qpre; [426,1157): tau 1/blk
#define K_CV   320
#define K_B    (K_CV)             // 320
#define K_REL  (K_B + 1)          // 321
#define K_QP   (K_REL + 101)      // 422
#define K_TAU  (K_QP + 4)         // 426
#define K_END  (K_TAU + 731)      // 1157

__global__ void __launch_bounds__(256)
prep_aux_kernel(const float* __restrict__ hidden,
                const float* __restrict__ rela,
                const int*   __restrict__ q_rel,
                const float* __restrict__ Ws,
                const float* __restrict__ Wr,
                const float* __restrict__ WqrW,
                const float* __restrict__ Wqrb,
                const float* __restrict__ Wtau,
                const float* __restrict__ Wh,
                const float* __restrict__ wt1,
                const float* __restrict__ bt1,
                const float* __restrict__ wt2,
                const float* __restrict__ bt2) {
    __shared__ float sh[16 * IN_DIM];
    const int tid = threadIdx.x;
    const int blk = blockIdx.x;

    if (blk < K_CV) {
        // ---- convert hidden (pad rows -> 0) ----
        const int total = NROWPAD * (IN_DIM / 4);
        const int stride = K_CV * 256;
        const float4* src = reinterpret_cast<const float4*>(hidden);
        ull* dh = reinterpret_cast<ull*>(gAh);
        ull* dl = reinterpret_cast<ull*>(gAl);
        const int limit = N_NODE * (IN_DIM / 4);
        for (int i = blk * 256 + tid; i < total; i += stride) {
            float4 v = (i < limit) ? src[i] : make_float4(0.f, 0.f, 0.f, 0.f);
            unsigned short h0, l0, h1, l1, h2, l2, h3, l3;
            cvt_hilo(v.x, h0, l0); cvt_hilo(v.y, h1, l1);
            cvt_hilo(v.z, h2, l2); cvt_hilo(v.w, h3, l3);
            dh[i] = (ull)h0 | ((ull)h1 << 16) | ((ull)h2 << 32) | ((ull)h3 << 48);
            dl[i] = (ull)l0 | ((ull)l1 << 16) | ((ull)l2 << 32) | ((ull)l3 << 48);
        }
    } else if (blk == K_B) {
        // ---- convert B = [Ws|Wh] ----
        for (int i = tid; i < IN_DIM * REC; i += 256) {
            int k = i / REC, n = i - k * REC;
            float v = (n < 64) ? Ws[k * ATTN_DIM + n] : Wh[k * OUT_DIM + (n - 64)];
            unsigned short h, l;
            cvt_hilo(v, h, l);
            gBh[i] = __ushort_as_bfloat16(h);
            gBl[i] = __ushort_as_bfloat16(l);
        }
    } else if (blk < K_QP) {
        // ---- rel table: 4 rels per block ----
        const int rb = (blk - K_REL) * 4;
        for (int i = tid; i < 4 * IN_DIM; i += 256) {
            int rr = i >> 7, k = i & 127;
            int r = rb + rr;
            sh[rr * IN_DIM + k] = (r < N_RELTOT) ? rela[(size_t)r * IN_DIM + k] : 0.f;
        }
        __syncthreads();
        for (int o = tid; o < 4 * REC; o += 256) {
            int rr = o / REC, c = o - rr * REC;
            int r = rb + rr;
            if (r >= N_RELTOT) continue;
            const float* hrow = sh + rr * IN_DIM;
            float acc = 0.f;
            if (c < 64) {
#pragma unroll 8
                for (int k = 0; k < IN_DIM; k++)
                    acc = fmaf(hrow[k], __ldg(Wr + k * ATTN_DIM + c), acc);
                h_rA[r * ATTN_DIM + c] = __float2half_rn(acc);
            } else {
                const int cc = c - 64;
#pragma unroll 8
                for (int k = 0; k < IN_DIM; k++)
                    acc = fmaf(hrow[k], __ldg(Wh + k * OUT_DIM + cc), acc);
            }
            g_rel[r * REC + c] = acc;
        }
    } else if (blk < K_TAU) {
        // ---- qpre: 16 queries per block ----
        const int qb = (blk - K_QP) * 16;
        for (int i = tid; i < 16 * IN_DIM; i += 256) {
            int qq = i >> 7, k = i & 127;
            int q = qb + qq;
            int rl = (q < N_QUERY) ? __ldg(q_rel + q) : 0;
            sh[qq * IN_DIM + k] = rela[(size_t)rl * IN_DIM + k];
        }
        __syncthreads();
        for (int o = tid; o < 16 * ATTN_DIM; o += 256) {
            int qq = o >> 6, c = o & 63;
            int q = qb + qq;
            if (q >= N_QUERY) continue;
            const float* hrow = sh + qq * IN_DIM;
            float acc = __ldg(Wqrb + c);
#pragma unroll 8
            for (int k = 0; k < IN_DIM; k++)
                acc = fmaf(hrow[k], __ldg(WqrW + k * ATTN_DIM + c), acc);
            g_qpre[q * ATTN_DIM + c] = acc;
            h_qA[q * ATTN_DIM + c] = __float2half_rn(acc);
        }
    } else {
        // ---- tau table: one t per block ----
        const int t = blk - K_TAU;
        const float dt = (float)(t - 365);
        if (tid < IN_DIM)
            sh[tid] = wt1[tid] * dt + bt1[tid] + sinf(fmaf(wt2[tid], dt, bt2[tid]));
        __syncthreads();
        if (tid < REC) {
            const int c = tid;
            float acc = 0.f;
            if (c < 64) {
#pragma unroll 8
                for (int k = 0; k < IN_DIM; k++)
                    acc = fmaf(sh[k], __ldg(Wtau + k * ATTN_DIM + c), acc);
                h_tA[t * ATTN_DIM + c] = __float2half_rn(acc);
            } else {
                const int cc = c - 64;
#pragma unroll 8
                for (int k = 0; k < IN_DIM; k++)
                    acc = fmaf(sh[k], __ldg(Wh + k * OUT_DIM + cc), acc);
            }
            g_tau[t * REC + c] = acc;
        }
    }
}

// ================= node GEMM (MLP-unrolled staging + fused fp16 epilogue) ===
#define N_TILE   391
#define GB       131
#define TPB      3
#define LDA 136
#define LDB 200
#define SA_H 0
#define SA_L (SA_H + 128 * LDA * 2)
#define SB_H (SA_L + 128 * LDA * 2)
#define SB_L (SB_H + 128 * LDB * 2)
#define SM1_TOT (SB_L + 128 * LDB * 2)     // 172032

__global__ void __launch_bounds__(256)
node_gemm_kernel() {
    extern __shared__ char smem[];
    __nv_bfloat16* Ah = reinterpret_cast<__nv_bfloat16*>(smem + SA_H);
    __nv_bfloat16* Al = reinterpret_cast<__nv_bfloat16*>(smem + SA_L);
    __nv_bfloat16* Bh = reinterpret_cast<__nv_bfloat16*>(smem + SB_H);
    __nv_bfloat16* Bl = reinterpret_cast<__nv_bfloat16*>(smem + SB_L);
    const int tid = threadIdx.x;
    const int wid = tid >> 5;
    const int lane = tid & 31;

    // stage B once: 12 iterations/thread, fully unrolled for MLP
    {
        const float4* sh4 = reinterpret_cast<const float4*>(gBh);
        const float4* sl4 = reinterpret_cast<const float4*>(gBl);
#pragma unroll
        for (int it = 0; it < 12; it++) {
            int i = it * 256 + tid;
            int k = i / 24, c = i - k * 24;
            *reinterpret_cast<float4*>(Bh + k * LDB + c * 8) = sh4[k * 24 + c];
            *reinterpret_cast<float4*>(Bl + k * LDB + c * 8) = sl4[k * 24 + c];
        }
    }

    wmma::fragment<wmma::matrix_a, 16, 16, 16, __nv_bfloat16, wmma::row_major> fah, fal;
    wmma::fragment<wmma::matrix_b, 16, 16, 16, __nv_bfloat16, wmma::row_major> fbh, fbl;

    for (int s = 0; s < TPB; s++) {
        const int tile = blockIdx.x * TPB + s;
        if (tile >= N_TILE) break;
        const int r0 = tile * 128;

        __syncthreads();
        {
            const float4* ah4 = reinterpret_cast<const float4*>(gAh);
            const float4* al4 = reinterpret_cast<const float4*>(gAl);
#pragma unroll
            for (int it = 0; it < 8; it++) {
                int i = it * 256 + tid;
                int row = i >> 4, c = i & 15;
                *reinterpret_cast<float4*>(Ah + row * LDA + c * 8) = ah4[(size_t)(r0 + row) * 16 + c];
                *reinterpret_cast<float4*>(Al + row * LDA + c * 8) = al4[(size_t)(r0 + row) * 16 + c];
            }
        }
        __syncthreads();

        wmma::fragment<wmma::accumulator, 16, 16, 16, float> acc[12];
#pragma unroll
        for (int ct = 0; ct < 12; ct++) wmma::fill_fragment(acc[ct], 0.f);

#pragma unroll
        for (int ks = 0; ks < 8; ks++) {
            wmma::load_matrix_sync(fah, Ah + wid * 16 * LDA + ks * 16, LDA);
            wmma::load_matrix_sync(fal, Al + wid * 16 * LDA + ks * 16, LDA);
#pragma unroll
            for (int ct = 0; ct < 12; ct++) {
                wmma::load_matrix_sync(fbh, Bh + ks * 16 * LDB + ct * 16, LDB);
                wmma::load_matrix_sync(fbl, Bl + ks * 16 * LDB + ct * 16, LDB);
                wmma::mma_sync(acc[ct], fah, fbh, acc[ct]);
                wmma::mma_sync(acc[ct], fah, fbl, acc[ct]);
                wmma::mma_sync(acc[ct], fal, fbh, acc[ct]);
            }
        }

        // epilogue: fp32 REC row to g_node
        float* dst = g_node + (size_t)(r0 + wid * 16) * REC;
#pragma unroll
        for (int ct = 0; ct < 12; ct++)
            wmma::store_matrix_sync(dst + ct * 16, acc[ct], REC, wmma::mem_row_major);

        // fused fp16 attn epilogue: park attn frags in (own strip of) A smem, convert
        // warp-private region: no cross-warp hazard; next-tile staging is after syncthreads
        float* abuf = reinterpret_cast<float*>(smem + SA_H) + wid * (16 * 64);
#pragma unroll
        for (int ct = 0; ct < 4; ct++)
            wmma::store_matrix_sync(abuf + ct * 16, acc[ct], 64, wmma::mem_row_major);
        __half* hdst = h_nA + (size_t)(r0 + wid * 16) * ATTN_DIM;
#pragma unroll
        for (int it = 0; it < 16; it++) {
            int idx = it * 32 + lane;          // 512 half2 slots = 16 rows x 32 pairs
            int rr = idx >> 5, cp = idx & 31;
            float2 v = *reinterpret_cast<float2*>(abuf + rr * 64 + cp * 2);
            *reinterpret_cast<__half2*>(hdst + rr * ATTN_DIM + cp * 2) =
                __floats2half2_rn(v.x, v.y);
        }
    }
}

// ================= edge kernel: fp16 attn gathers + REDG =================
__global__ void __launch_bounds__(256)
edge_kernel(const int* __restrict__ edges,
            const int* __restrict__ q_tau,
            const float* __restrict__ waW,
            const float* __restrict__ wab,
            float* __restrict__ out) {
    const int gw   = (blockIdx.x * blockDim.x + threadIdx.x) >> 5;
    const int lane = threadIdx.x & 31;
    const int e0   = gw << 1;
    if (e0 >= N_EDGE) return;

    const int h  = lane >> 4;
    const int sl = lane & 15;
    const int e  = e0 + h;

    const int* er = edges + (size_t)e * 7;
    const int r_idx = __ldg(er + 0);
    const int rel   = __ldg(er + 2);
    const int tauv  = __ldg(er + 4);
    const int sub   = __ldg(er + 5);
    const int obj   = __ldg(er + 6);

    const int tq = __ldg(q_tau + r_idx);
    const int t  = (tauv >= 0 ? tauv - tq : 0) + 365;

    // fp16 attention gathers: one 8B load per table per lane
    uint2 un = *reinterpret_cast<const uint2*>(h_nA + (size_t)sub * ATTN_DIM + sl * 4);
    uint2 ur = *reinterpret_cast<const uint2*>(h_rA + rel   * ATTN_DIM + sl * 4);
    uint2 ut = *reinterpret_cast<const uint2*>(h_tA + t     * ATTN_DIM + sl * 4);
    uint2 uq = *reinterpret_cast<const uint2*>(h_qA + r_idx * ATTN_DIM + sl * 4);

    float2 fn0 = __half22float2(*reinterpret_cast<__half2*>(&un.x));
    float2 fn1 = __half22float2(*reinterpret_cast<__half2*>(&un.y));
    float2 fr0 = __half22float2(*reinterpret_cast<__half2*>(&ur.x));
    float2 fr1 = __half22float2(*reinterpret_cast<__half2*>(&ur.y));
    float2 ft0 = __half22float2(*reinterpret_cast<__half2*>(&ut.x));
    float2 ft1 = __half22float2(*reinterpret_cast<__half2*>(&ut.y));
    float2 fq0 = __half22float2(*reinterpret_cast<__half2*>(&uq.x));
    float2 fq1 = __half22float2(*reinterpret_cast<__half2*>(&uq.y));

    float4 w = reinterpret_cast<const float4*>(waW)[sl];
    float p0 = fmaxf(fn0.x + fr0.x + ft0.x + fq0.x, 0.f);
    float p1 = fmaxf(fn0.y + fr0.y + ft0.y + fq0.y, 0.f);
    float p2 = fmaxf(fn1.x + fr1.x + ft1.x + fq1.x, 0.f);
    float p3 = fmaxf(fn1.y + fr1.y + ft1.y + fq1.y, 0.f);
    float s = fmaf(p0, w.x, fmaf(p1, w.y, fmaf(p2, w.z, p3 * w.w)));
#pragma unroll
    for (int off = 8; off > 0; off >>= 1)
        s += __shfl_xor_sync(0xFFFFFFFFu, s, off);
    const float alpha = 1.f / (1.f + __expf(-(s + __ldg(wab))));

    // projected message (fp32): 8 floats per lane from each table
    const float4* np = reinterpret_cast<const float4*>(g_node + (size_t)sub * REC);
    const float4* rp = reinterpret_cast<const float4*>(g_rel  + rel   * REC);
    const float4* tp = reinterpret_cast<const float4*>(g_tau  + t     * REC);
    const int mo = 16 + sl * 2;
    float4 n0 = np[mo], n1 = np[mo + 1];
    float4 r0 = rp[mo], r1 = rp[mo + 1];
    float4 t0 = tp[mo], t1 = tp[mo + 1];

    float4 m0, m1;
    m0.x = alpha * (n0.x + r0.x + t0.x);  m0.y = alpha * (n0.y + r0.y + t0.y);
    m0.z = alpha * (n0.z + r0.z + t0.z);  m0.w = alpha * (n0.w + r0.w + t0.w);
    m1.x = alpha * (n1.x + r1.x + t1.x);  m1.y = alpha * (n1.y + r1.y + t1.y);
    m1.z = alpha * (n1.z + r1.z + t1.z);  m1.w = alpha * (n1.w + r1.w + t1.w);

    float* dst = out + (size_t)obj * OUT_DIM + sl * 8;
    asm volatile("red.global.add.v4.f32 [%0], {%1,%2,%3,%4};"
                 :: "l"(dst), "f"(m0.x), "f"(m0.y), "f"(m0.z), "f"(m0.w) : "memory");
    asm volatile("red.global.add.v4.f32 [%0], {%1,%2,%3,%4};"
                 :: "l"(dst + 4), "f"(m1.x), "f"(m1.y), "f"(m1.z), "f"(m1.w) : "memory");
}

// ================= launcher =================
extern "C" void kernel_launch(void* const* d_in, const int* in_sizes, int n_in,
                              void* d_out, int out_size) {
    int base = 5;
    if (n_in > 5 && in_sizes[5] == 1) base = 6;

    const int*   q_rel  = (const int*)  d_in[1];
    const int*   q_tau  = (const int*)  d_in[2];
    const float* hidden = (const float*)d_in[3];
    const int*   edges  = (const int*)  d_in[4];
    const float* rela   = (const float*)d_in[base + 1];
    const float* Ws     = (const float*)d_in[base + 2];
    const float* Wr     = (const float*)d_in[base + 3];
    const float* WqrW   = (const float*)d_in[base + 4];
    const float* Wqrb   = (const float*)d_in[base + 5];
    const float* Wtau   = (const float*)d_in[base + 6];
    const float* waW    = (const float*)d_in[base + 7];
    const float* wab    = (const float*)d_in[base + 8];
    const float* Wh     = (const float*)d_in[base + 9];
    const float* wt1    = (const float*)d_in[base + 10];
    const float* bt1    = (const float*)d_in[base + 11];
    const float* wt2    = (const float*)d_in[base + 12];
    const float* bt2    = (const float*)d_in[base + 13];
    float* out = (float*)d_out;

    cudaFuncSetAttribute(node_gemm_kernel,
                         cudaFuncAttributeMaxDynamicSharedMemorySize, SM1_TOT);

    cudaMemsetAsync(out, 0, (size_t)out_size * sizeof(float), 0);

    prep_aux_kernel<<<K_END, 256>>>(
        hidden, rela, q_rel, Ws, Wr, WqrW, Wqrb, Wtau, Wh,
        wt1, bt1, wt2, bt2);

    node_gemm_kernel<<<GB, 256, SM1_TOT>>>();

    edge_kernel<<<N_EDGE / 16, 256>>>(edges, q_tau, waW, wab, out);
}

// round 16
// speedup vs baseline: 1.6135x; 1.0916x over previous
#include <cuda_runtime.h>
#include <cuda_bf16.h>
#include <cuda_fp16.h>
#include <mma.h>
#include <math.h>
#include <stdint.h>

using namespace nvcuda;
typedef unsigned long long ull;

#define N_NODE   50000
#define N_EDGE   500000
#define N_QUERY  64
#define IN_DIM   128
#define OUT_DIM  128
#define ATTN_DIM 64
#define N_RELTOT 401
#define N_TAU    731
#define REC      192        // 64 attn cols + 128 msg cols (GEMM N)
#define NROWPAD  50048      // 391 * 128

// ---- scratch (device globals) ----
__device__ __nv_bfloat16 gAh[NROWPAD * IN_DIM];
__device__ __nv_bfloat16 gAl[NROWPAD * IN_DIM];
__device__ __nv_bfloat16 gBh[IN_DIM * REC];
__device__ __nv_bfloat16 gBl[IN_DIM * REC];
// fp16 attention tables (64 cols)
__device__ __align__(16) __half h_nA[NROWPAD  * ATTN_DIM];
__device__ __align__(16) __half h_rA[N_RELTOT * ATTN_DIM];
__device__ __align__(16) __half h_tA[N_TAU    * ATTN_DIM];
__device__ __align__(16) __half h_qA[N_QUERY  * ATTN_DIM];
// fp16 projected-message tables (128 cols)
__device__ __align__(16) __half h_nM[NROWPAD  * OUT_DIM];
__device__ __align__(16) __half h_rM[N_RELTOT * OUT_DIM];
__device__ __align__(16) __half h_tM[N_TAU    * OUT_DIM];
// packed edge meta {r_idx | t<<16, rel, sub, obj}
__device__ int4 g_emeta[N_EDGE];

__device__ __forceinline__ void cvt_hilo(float v, unsigned short& h, unsigned short& l) {
    __nv_bfloat16 hb = __float2bfloat16_rn(v);
    __nv_bfloat16 lb = __float2bfloat16_rn(v - __bfloat162float(hb));
    h = __bfloat16_as_ushort(hb);
    l = __bfloat16_as_ushort(lb);
}

// ================= kernel 0: convert + meta pack + small tables =================
// [0,320): convert hidden; [320,480): meta pack; 480: B convert;
// [481,582): rel 4/blk; [582,586): qpre; [586,1317): tau 1/blk
#define K_CV   320
#define K_META (K_CV)             // [320,480)
#define K_B    (K_META + 160)     // 480
#define K_REL  (K_B + 1)          // 481
#define K_QP   (K_REL + 101)      // 582
#define K_TAU  (K_QP + 4)         // 586
#define K_END  (K_TAU + 731)      // 1317

__global__ void __launch_bounds__(256)
prep_aux_kernel(const float* __restrict__ hidden,
                const float* __restrict__ rela,
                const int*   __restrict__ q_rel,
                const int*   __restrict__ q_tau,
                const int*   __restrict__ edges,
                const float* __restrict__ Ws,
                const float* __restrict__ Wr,
                const float* __restrict__ WqrW,
                const float* __restrict__ Wqrb,
                const float* __restrict__ Wtau,
                const float* __restrict__ Wh,
                const float* __restrict__ wt1,
                const float* __restrict__ bt1,
                const float* __restrict__ wt2,
                const float* __restrict__ bt2) {
    __shared__ float sh[16 * IN_DIM];
    const int tid = threadIdx.x;
    const int blk = blockIdx.x;

    if (blk < K_CV) {
        // ---- convert hidden (pad rows -> 0) ----
        const int total = NROWPAD * (IN_DIM / 4);
        const int stride = K_CV * 256;
        const float4* src = reinterpret_cast<const float4*>(hidden);
        ull* dh = reinterpret_cast<ull*>(gAh);
        ull* dl = reinterpret_cast<ull*>(gAl);
        const int limit = N_NODE * (IN_DIM / 4);
        for (int i = blk * 256 + tid; i < total; i += stride) {
            float4 v = (i < limit) ? src[i] : make_float4(0.f, 0.f, 0.f, 0.f);
            unsigned short h0, l0, h1, l1, h2, l2, h3, l3;
            cvt_hilo(v.x, h0, l0); cvt_hilo(v.y, h1, l1);
            cvt_hilo(v.z, h2, l2); cvt_hilo(v.w, h3, l3);
            dh[i] = (ull)h0 | ((ull)h1 << 16) | ((ull)h2 << 32) | ((ull)h3 << 48);
            dl[i] = (ull)l0 | ((ull)l1 << 16) | ((ull)l2 << 32) | ((ull)l3 << 48);
        }
    } else if (blk < K_B) {
        // ---- pack edge meta ----
        const int stride = 160 * 256;
        for (int e = (blk - K_META) * 256 + tid; e < N_EDGE; e += stride) {
            const int* er = edges + (size_t)e * 7;
            int r_idx = __ldg(er + 0);
            int rel   = __ldg(er + 2);
            int tauv  = __ldg(er + 4);
            int sub   = __ldg(er + 5);
            int obj   = __ldg(er + 6);
            int tq = __ldg(q_tau + r_idx);
            int t = (tauv >= 0 ? tauv - tq : 0) + 365;    // 0..730
            int4 m;
            m.x = r_idx | (t << 16);
            m.y = rel; m.z = sub; m.w = obj;
            g_emeta[e] = m;
        }
    } else if (blk == K_B) {
        // ---- convert B = [Ws|Wh] ----
        for (int i = tid; i < IN_DIM * REC; i += 256) {
            int k = i / REC, n = i - k * REC;
            float v = (n < 64) ? Ws[k * ATTN_DIM + n] : Wh[k * OUT_DIM + (n - 64)];
            unsigned short h, l;
            cvt_hilo(v, h, l);
            gBh[i] = __ushort_as_bfloat16(h);
            gBl[i] = __ushort_as_bfloat16(l);
        }
    } else if (blk < K_QP) {
        // ---- rel table: 4 rels per block ----
        const int rb = (blk - K_REL) * 4;
        for (int i = tid; i < 4 * IN_DIM; i += 256) {
            int rr = i >> 7, k = i & 127;
            int r = rb + rr;
            sh[rr * IN_DIM + k] = (r < N_RELTOT) ? rela[(size_t)r * IN_DIM + k] : 0.f;
        }
        __syncthreads();
        for (int o = tid; o < 4 * REC; o += 256) {
            int rr = o / REC, c = o - rr * REC;
            int r = rb + rr;
            if (r >= N_RELTOT) continue;
            const float* hrow = sh + rr * IN_DIM;
            float acc = 0.f;
            if (c < 64) {
#pragma unroll 8
                for (int k = 0; k < IN_DIM; k++)
                    acc = fmaf(hrow[k], __ldg(Wr + k * ATTN_DIM + c), acc);
                h_rA[r * ATTN_DIM + c] = __float2half_rn(acc);
            } else {
                const int cc = c - 64;
#pragma unroll 8
                for (int k = 0; k < IN_DIM; k++)
                    acc = fmaf(hrow[k], __ldg(Wh + k * OUT_DIM + cc), acc);
                h_rM[r * OUT_DIM + cc] = __float2half_rn(acc);
            }
        }
    } else if (blk < K_TAU) {
        // ---- qpre: 16 queries per block ----
        const int qb = (blk - K_QP) * 16;
        for (int i = tid; i < 16 * IN_DIM; i += 256) {
            int qq = i >> 7, k = i & 127;
            int q = qb + qq;
            int rl = (q < N_QUERY) ? __ldg(q_rel + q) : 0;
            sh[qq * IN_DIM + k] = rela[(size_t)rl * IN_DIM + k];
        }
        __syncthreads();
        for (int o = tid; o < 16 * ATTN_DIM; o += 256) {
            int qq = o >> 6, c = o & 63;
            int q = qb + qq;
            if (q >= N_QUERY) continue;
            const float* hrow = sh + qq * IN_DIM;
            float acc = __ldg(Wqrb + c);
#pragma unroll 8
            for (int k = 0; k < IN_DIM; k++)
                acc = fmaf(hrow[k], __ldg(WqrW + k * ATTN_DIM + c), acc);
            h_qA[q * ATTN_DIM + c] = __float2half_rn(acc);
        }
    } else {
        // ---- tau table: one t per block ----
        const int t = blk - K_TAU;
        const float dt = (float)(t - 365);
        if (tid < IN_DIM)
            sh[tid] = wt1[tid] * dt + bt1[tid] + sinf(fmaf(wt2[tid], dt, bt2[tid]));
        __syncthreads();
        if (tid < REC) {
            const int c = tid;
            float acc = 0.f;
            if (c < 64) {
#pragma unroll 8
                for (int k = 0; k < IN_DIM; k++)
                    acc = fmaf(sh[k], __ldg(Wtau + k * ATTN_DIM + c), acc);
                h_tA[t * ATTN_DIM + c] = __float2half_rn(acc);
            } else {
                const int cc = c - 64;
#pragma unroll 8
                for (int k = 0; k < IN_DIM; k++)
                    acc = fmaf(sh[k], __ldg(Wh + k * OUT_DIM + cc), acc);
                h_tM[t * OUT_DIM + cc] = __float2half_rn(acc);
            }
        }
    }
}

// ================= node GEMM: all-fp16 epilogue =================
#define N_TILE   391
#define GB       131
#define TPB      3
#define LDA 136
#define LDB 200
#define SA_H 0
#define SA_L (SA_H + 128 * LDA * 2)
#define SB_H (SA_L + 128 * LDA * 2)
#define SB_L (SB_H + 128 * LDB * 2)
#define SM1_TOT (SB_L + 128 * LDB * 2)     // 172032

__global__ void __launch_bounds__(256)
node_gemm_kernel() {
    extern __shared__ char smem[];
    __nv_bfloat16* Ah = reinterpret_cast<__nv_bfloat16*>(smem + SA_H);
    __nv_bfloat16* Al = reinterpret_cast<__nv_bfloat16*>(smem + SA_L);
    __nv_bfloat16* Bh = reinterpret_cast<__nv_bfloat16*>(smem + SB_H);
    __nv_bfloat16* Bl = reinterpret_cast<__nv_bfloat16*>(smem + SB_L);
    const int tid = threadIdx.x;
    const int wid = tid >> 5;
    const int lane = tid & 31;

    // stage B once (unrolled for MLP)
    {
        const float4* sh4 = reinterpret_cast<const float4*>(gBh);
        const float4* sl4 = reinterpret_cast<const float4*>(gBl);
#pragma unroll
        for (int it = 0; it < 12; it++) {
            int i = it * 256 + tid;
            int k = i / 24, c = i - k * 24;
            *reinterpret_cast<float4*>(Bh + k * LDB + c * 8) = sh4[k * 24 + c];
            *reinterpret_cast<float4*>(Bl + k * LDB + c * 8) = sl4[k * 24 + c];
        }
    }

    wmma::fragment<wmma::matrix_a, 16, 16, 16, __nv_bfloat16, wmma::row_major> fah, fal;
    wmma::fragment<wmma::matrix_b, 16, 16, 16, __nv_bfloat16, wmma::row_major> fbh, fbl;

    for (int s = 0; s < TPB; s++) {
        const int tile = blockIdx.x * TPB + s;
        if (tile >= N_TILE) break;
        const int r0 = tile * 128;

        __syncthreads();
        {
            const float4* ah4 = reinterpret_cast<const float4*>(gAh);
            const float4* al4 = reinterpret_cast<const float4*>(gAl);
#pragma unroll
            for (int it = 0; it < 8; it++) {
                int i = it * 256 + tid;
                int row = i >> 4, c = i & 15;
                *reinterpret_cast<float4*>(Ah + row * LDA + c * 8) = ah4[(size_t)(r0 + row) * 16 + c];
                *reinterpret_cast<float4*>(Al + row * LDA + c * 8) = al4[(size_t)(r0 + row) * 16 + c];
            }
        }
        __syncthreads();

        wmma::fragment<wmma::accumulator, 16, 16, 16, float> acc[12];
#pragma unroll
        for (int ct = 0; ct < 12; ct++) wmma::fill_fragment(acc[ct], 0.f);

#pragma unroll
        for (int ks = 0; ks < 8; ks++) {
            wmma::load_matrix_sync(fah, Ah + wid * 16 * LDA + ks * 16, LDA);
            wmma::load_matrix_sync(fal, Al + wid * 16 * LDA + ks * 16, LDA);
#pragma unroll
            for (int ct = 0; ct < 12; ct++) {
                wmma::load_matrix_sync(fbh, Bh + ks * 16 * LDB + ct * 16, LDB);
                wmma::load_matrix_sync(fbl, Bl + ks * 16 * LDB + ct * 16, LDB);
                wmma::mma_sync(acc[ct], fah, fbh, acc[ct]);
                wmma::mma_sync(acc[ct], fah, fbl, acc[ct]);
                wmma::mma_sync(acc[ct], fal, fbh, acc[ct]);
            }
        }

        // epilogue: park 4 frags at a time in warp-private smem, convert to fp16
        float* abuf = reinterpret_cast<float*>(smem + SA_H) + wid * (16 * 64);

        // group 0: attn cols 0..63 -> h_nA
#pragma unroll
        for (int ct = 0; ct < 4; ct++)
            wmma::store_matrix_sync(abuf + ct * 16, acc[ct], 64, wmma::mem_row_major);
        __syncwarp();
        {
            __half* hdst = h_nA + (size_t)(r0 + wid * 16) * ATTN_DIM;
#pragma unroll
            for (int it = 0; it < 16; it++) {
                int idx = it * 32 + lane;
                int rr = idx >> 5, cp = idx & 31;
                float2 v = *reinterpret_cast<float2*>(abuf + rr * 64 + cp * 2);
                *reinterpret_cast<__half2*>(hdst + rr * ATTN_DIM + cp * 2) =
                    __floats2half2_rn(v.x, v.y);
            }
        }
        __syncwarp();

        // group 1: msg cols 0..63 -> h_nM[:, 0:64)
#pragma unroll
        for (int ct = 4; ct < 8; ct++)
            wmma::store_matrix_sync(abuf + (ct - 4) * 16, acc[ct], 64, wmma::mem_row_major);
        __syncwarp();
        {
            __half* hdst = h_nM + (size_t)(r0 + wid * 16) * OUT_DIM;
#pragma unroll
            for (int it = 0; it < 16; it++) {
                int idx = it * 32 + lane;
                int rr = idx >> 5, cp = idx & 31;
                float2 v = *reinterpret_cast<float2*>(abuf + rr * 64 + cp * 2);
                *reinterpret_cast<__half2*>(hdst + rr * OUT_DIM + cp * 2) =
                    __floats2half2_rn(v.x, v.y);
            }
        }
        __syncwarp();

        // group 2: msg cols 64..127 -> h_nM[:, 64:128)
#pragma unroll
        for (int ct = 8; ct < 12; ct++)
            wmma::store_matrix_sync(abuf + (ct - 8) * 16, acc[ct], 64, wmma::mem_row_major);
        __syncwarp();
        {
            __half* hdst = h_nM + (size_t)(r0 + wid * 16) * OUT_DIM + 64;
#pragma unroll
            for (int it = 0; it < 16; it++) {
                int idx = it * 32 + lane;
                int rr = idx >> 5, cp = idx & 31;
                float2 v = *reinterpret_cast<float2*>(abuf + rr * 64 + cp * 2);
                *reinterpret_cast<__half2*>(hdst + rr * OUT_DIM + cp * 2) =
                    __floats2half2_rn(v.x, v.y);
            }
        }
        __syncwarp();
    }
}

// ================= edge kernel: packed meta + all-fp16 gathers =================
__device__ __forceinline__ float2 h22f2(unsigned u) {
    return __half22float2(*reinterpret_cast<__half2*>(&u));
}

__global__ void __launch_bounds__(256)
edge_kernel(const float* __restrict__ waW,
            const float* __restrict__ wab,
            float* __restrict__ out) {
    const int gw   = (blockIdx.x * blockDim.x + threadIdx.x) >> 5;
    const int lane = threadIdx.x & 31;
    const int e0   = gw << 1;
    if (e0 >= N_EDGE) return;

    const int h  = lane >> 4;
    const int sl = lane & 15;
    const int e  = e0 + h;

    const int4 m = g_emeta[e];
    const int r_idx = m.x & 0xFFFF;
    const int t     = m.x >> 16;
    const int rel   = m.y;
    const int sub   = m.z;
    const int obj   = m.w;

    // attention gathers: 8B/lane/table
    uint2 un = *reinterpret_cast<const uint2*>(h_nA + (size_t)sub * ATTN_DIM + sl * 4);
    uint2 ur = *reinterpret_cast<const uint2*>(h_rA + rel   * ATTN_DIM + sl * 4);
    uint2 ut = *reinterpret_cast<const uint2*>(h_tA + t     * ATTN_DIM + sl * 4);
    uint2 uq = *reinterpret_cast<const uint2*>(h_qA + r_idx * ATTN_DIM + sl * 4);

    float2 fn0 = h22f2(un.x), fn1 = h22f2(un.y);
    float2 fr0 = h22f2(ur.x), fr1 = h22f2(ur.y);
    float2 ft0 = h22f2(ut.x), ft1 = h22f2(ut.y);
    float2 fq0 = h22f2(uq.x), fq1 = h22f2(uq.y);

    float4 w = reinterpret_cast<const float4*>(waW)[sl];
    float p0 = fmaxf(fn0.x + fr0.x + ft0.x + fq0.x, 0.f);
    float p1 = fmaxf(fn0.y + fr0.y + ft0.y + fq0.y, 0.f);
    float p2 = fmaxf(fn1.x + fr1.x + ft1.x + fq1.x, 0.f);
    float p3 = fmaxf(fn1.y + fr1.y + ft1.y + fq1.y, 0.f);
    float s = fmaf(p0, w.x, fmaf(p1, w.y, fmaf(p2, w.z, p3 * w.w)));
#pragma unroll
    for (int off = 8; off > 0; off >>= 1)
        s += __shfl_xor_sync(0xFFFFFFFFu, s, off);
    const float alpha = 1.f / (1.f + __expf(-(s + __ldg(wab))));

    // projected message gathers: 16B/lane/table (8 halves)
    uint4 an = *reinterpret_cast<const uint4*>(h_nM + (size_t)sub * OUT_DIM + sl * 8);
    uint4 ar = *reinterpret_cast<const uint4*>(h_rM + rel   * OUT_DIM + sl * 8);
    uint4 at = *reinterpret_cast<const uint4*>(h_tM + t     * OUT_DIM + sl * 8);

    float2 a0 = h22f2(an.x), a1 = h22f2(an.y), a2 = h22f2(an.z), a3 = h22f2(an.w);
    float2 b0 = h22f2(ar.x), b1 = h22f2(ar.y), b2 = h22f2(ar.z), b3 = h22f2(ar.w);
    float2 c0 = h22f2(at.x), c1 = h22f2(at.y), c2 = h22f2(at.z), c3 = h22f2(at.w);

    float4 m0, m1;
    m0.x = alpha * (a0.x + b0.x + c0.x);  m0.y = alpha * (a0.y + b0.y + c0.y);
    m0.z = alpha * (a1.x + b1.x + c1.x);  m0.w = alpha * (a1.y + b1.y + c1.y);
    m1.x = alpha * (a2.x + b2.x + c2.x);  m1.y = alpha * (a2.y + b2.y + c2.y);
    m1.z = alpha * (a3.x + b3.x + c3.x);  m1.w = alpha * (a3.y + b3.y + c3.y);

    float* dst = out + (size_t)obj * OUT_DIM + sl * 8;
    asm volatile("red.global.add.v4.f32 [%0], {%1,%2,%3,%4};"
                 :: "l"(dst), "f"(m0.x), "f"(m0.y), "f"(m0.z), "f"(m0.w) : "memory");
    asm volatile("red.global.add.v4.f32 [%0], {%1,%2,%3,%4};"
                 :: "l"(dst + 4), "f"(m1.x), "f"(m1.y), "f"(m1.z), "f"(m1.w) : "memory");
}

// ================= launcher =================
extern "C" void kernel_launch(void* const* d_in, const int* in_sizes, int n_in,
                              void* d_out, int out_size) {
    int base = 5;
    if (n_in > 5 && in_sizes[5] == 1) base = 6;

    const int*   q_rel  = (const int*)  d_in[1];
    const int*   q_tau  = (const int*)  d_in[2];
    const float* hidden = (const float*)d_in[3];
    const int*   edges  = (const int*)  d_in[4];
    const float* rela   = (const float*)d_in[base + 1];
    const float* Ws     = (const float*)d_in[base + 2];
    const float* Wr     = (const float*)d_in[base + 3];
    const float* WqrW   = (const float*)d_in[base + 4];
    const float* Wqrb   = (const float*)d_in[base + 5];
    const float* Wtau   = (const float*)d_in[base + 6];
    const float* waW    = (const float*)d_in[base + 7];
    const float* wab    = (const float*)d_in[base + 8];
    const float* Wh     = (const float*)d_in[base + 9];
    const float* wt1    = (const float*)d_in[base + 10];
    const float* bt1    = (const float*)d_in[base + 11];
    const float* wt2    = (const float*)d_in[base + 12];
    const float* bt2    = (const float*)d_in[base + 13];
    float* out = (float*)d_out;

    cudaFuncSetAttribute(node_gemm_kernel,
                         cudaFuncAttributeMaxDynamicSharedMemorySize, SM1_TOT);

    cudaMemsetAsync(out, 0, (size_t)out_size * sizeof(float), 0);

    prep_aux_kernel<<<K_END, 256>>>(
        hidden, rela, q_rel, q_tau, edges, Ws, Wr, WqrW, Wqrb, Wtau, Wh,
        wt1, bt1, wt2, bt2);

    node_gemm_kernel<<<GB, 256, SM1_TOT>>>();

    edge_kernel<<<N_EDGE / 16, 256>>>(waW, wab, out);
}